// round 2
// baseline (speedup 1.0000x reference)
#include <cuda_runtime.h>
#include <math.h>

#define B_   16
#define N_   1024
#define C2_  64
#define D_   32
#define H_   64
#define NC_  10
#define EPSF 1e-11f
#define TILE 128

// scratch (static device globals — no allocation)
__device__ float g_fc[B_ * N_ * H_];   // relu(first_capsule), 4 MB
__device__ float g_v[B_ * N_];         // fc_n . u
__device__ float g_u[B_ * H_];         // sum_k scale_k * sec_k
__device__ float g_S[B_];              // sum_k scale_k
__device__ float g_c[B_];              // sum_k scale_k * |sec_k|^2

// ---------------------------------------------------------------------------
// Kernel 1: per-batch prep. One block per batch.
//   squash(second_capsule) -> top-8 by sn (monotonic with s) -> gather
//   squash(class_capsule[y]) -> append
//   sec = relu(secin @ W1^T + b1)  [9,64]
//   fold into S, u[64], c
// ---------------------------------------------------------------------------
__global__ __launch_bounds__(256) void prep_kernel(
    const float* __restrict__ second, const float* __restrict__ classc,
    const int* __restrict__ y, const float* __restrict__ W1,
    const float* __restrict__ b1)
{
    int b = blockIdx.x;
    int t = threadIdx.x;

    __shared__ float s_sn[C2_];
    __shared__ float s_scu[C2_][D_];
    __shared__ float s_secin[9][D_];
    __shared__ float s_scale[9];
    __shared__ int   s_idx[8];
    __shared__ float s_sec[9][H_];

    if (t < C2_) {
        const float* p = second + (b * C2_ + t) * D_;
        float sn = 0.f;
        #pragma unroll
        for (int d = 0; d < D_; d++) { float x = p[d]; sn += x * x; }
        s_sn[t] = sn;
        float inv = 1.0f / sqrtf(sn + EPSF);
        #pragma unroll
        for (int d = 0; d < D_; d++) s_scu[t][d] = p[d] * inv;
    }
    __syncthreads();

    if (t == 0) {
        // top-8 selection over 64 values (set only; order irrelevant, we sum over k)
        unsigned long long used = 0ull;
        for (int k = 0; k < 8; k++) {
            float best = -1.f; int bi = 0;
            for (int c = 0; c < C2_; c++)
                if (!((used >> c) & 1ull) && s_sn[c] > best) { best = s_sn[c]; bi = c; }
            used |= (1ull << bi);
            s_idx[k]   = bi;
            s_scale[k] = s_sn[bi] / (1.f + s_sn[bi]);
        }
        // true-class capsule index: robust to int32 or float32 encoding of y
        int yb = y[b];
        if ((unsigned)yb >= (unsigned)NC_) {
            float yf = __int_as_float(yb);
            yb = (int)yf;
            if ((unsigned)yb >= (unsigned)NC_) yb = 0;
        }
        const float* cp = classc + (b * NC_ + yb) * D_;
        float sn = 0.f;
        for (int d = 0; d < D_; d++) sn += cp[d] * cp[d];
        float inv = 1.f / sqrtf(sn + EPSF);
        for (int d = 0; d < D_; d++) s_secin[8][d] = cp[d] * inv;
        s_scale[8] = sn / (1.f + sn);
    }
    __syncthreads();

    if (t < 8 * D_) {
        int k = t / D_, d = t % D_;
        s_secin[k][d] = s_scu[s_idx[k]][d];
    }
    __syncthreads();

    // sec[k][h] = relu(sum_d secin[k][d] * W1[h][d] + b1[h]) ; 9*64 = 576 outputs
    for (int o = t; o < 9 * H_; o += 256) {
        int k = o / H_, h = o % H_;
        float acc = b1[h];
        #pragma unroll
        for (int d = 0; d < D_; d++) acc += s_secin[k][d] * W1[h * D_ + d];
        s_sec[k][h] = fmaxf(acc, 0.f);
    }
    __syncthreads();

    if (t < H_) {
        float uh = 0.f;
        #pragma unroll
        for (int k = 0; k < 9; k++) uh += s_scale[k] * s_sec[k][t];
        g_u[b * H_ + t] = uh;
    }
    if (t == 0) {
        float S = 0.f, cb = 0.f;
        for (int k = 0; k < 9; k++) {
            S += s_scale[k];
            float ss = 0.f;
            for (int h = 0; h < H_; h++) ss += s_sec[k][h] * s_sec[k][h];
            cb += s_scale[k] * ss;
        }
        g_S[b] = S;
        g_c[b] = cb;
    }
}

// ---------------------------------------------------------------------------
// Kernel 2: fc = relu(first_capsule) -> g_fc ; v[b,n] = fc_n . u[b]
// One warp per row (B*N = 16384 rows). 256 threads/block = 8 rows/block.
// ---------------------------------------------------------------------------
__global__ __launch_bounds__(256) void fc_kernel(const float* __restrict__ first)
{
    int gwarp = (blockIdx.x * blockDim.x + threadIdx.x) >> 5;
    int lane  = threadIdx.x & 31;
    if (gwarp >= B_ * N_) return;
    int b = gwarp >> 10;

    const float* p = first + (size_t)gwarp * H_;
    float f0 = fmaxf(p[lane], 0.f);
    float f1 = fmaxf(p[lane + 32], 0.f);
    g_fc[(size_t)gwarp * H_ + lane]      = f0;
    g_fc[(size_t)gwarp * H_ + lane + 32] = f1;

    float partial = f0 * g_u[b * H_ + lane] + f1 * g_u[b * H_ + lane + 32];
    #pragma unroll
    for (int o = 16; o; o >>= 1) partial += __shfl_xor_sync(0xFFFFFFFFu, partial, o);
    if (lane == 0) g_v[gwarp] = partial;
}

// ---------------------------------------------------------------------------
// Kernel 3: per-batch Gram matrix with fused epilogue + row mask.
//   out[b,n,m] = mask[b,n] ? S*(fc_n.fc_m) + v[n] + v[m] + c : 0
// 128x128 tile per block, 256 threads, 8x8 micro-tile per thread, K=64 resident.
// Mask is read as a 32-bit word (nonzero test) — valid for both float32 and
// int32 encodings of a jax bool array.
// ---------------------------------------------------------------------------
__global__ __launch_bounds__(256) void gram_kernel(
    const unsigned int* __restrict__ mask, float* __restrict__ out)
{
    extern __shared__ float smem[];
    float* As = smem;                 // [64][128]
    float* Bs = smem + 64 * TILE;     // [64][128]

    int mt = blockIdx.x;              // column tile (m)
    int nt = blockIdx.y;              // row tile (n)
    int b  = blockIdx.z;
    int t  = threadIdx.x;

    const float* fc = g_fc + (size_t)b * N_ * H_;
    int n0 = nt * TILE;
    int m0 = mt * TILE;

    // Load both 128x64 fp32 tiles, transposed into k-major smem.
    #pragma unroll
    for (int it = 0; it < 8; it++) {
        int flat = t + it * 256;          // 0..2047
        int row  = flat & 127;
        int kq   = flat >> 7;             // 0..15 (float4 index along k)
        float4 va = *(const float4*)(fc + (size_t)(n0 + row) * H_ + kq * 4);
        As[(kq * 4 + 0) * TILE + row] = va.x;
        As[(kq * 4 + 1) * TILE + row] = va.y;
        As[(kq * 4 + 2) * TILE + row] = va.z;
        As[(kq * 4 + 3) * TILE + row] = va.w;
        float4 vb = *(const float4*)(fc + (size_t)(m0 + row) * H_ + kq * 4);
        Bs[(kq * 4 + 0) * TILE + row] = vb.x;
        Bs[(kq * 4 + 1) * TILE + row] = vb.y;
        Bs[(kq * 4 + 2) * TILE + row] = vb.z;
        Bs[(kq * 4 + 3) * TILE + row] = vb.w;
    }
    __syncthreads();

    int tx = t & 15;    // micro-tile column group (m)
    int ty = t >> 4;    // micro-tile row group (n)

    float acc[8][8];
    #pragma unroll
    for (int i = 0; i < 8; i++)
        #pragma unroll
        for (int j = 0; j < 8; j++) acc[i][j] = 0.f;

    #pragma unroll 4
    for (int kk = 0; kk < 64; kk++) {
        float4 a0 = *(const float4*)(As + kk * TILE + ty * 8);
        float4 a1 = *(const float4*)(As + kk * TILE + ty * 8 + 4);
        float4 b0 = *(const float4*)(Bs + kk * TILE + tx * 8);
        float4 b1 = *(const float4*)(Bs + kk * TILE + tx * 8 + 4);
        float ar[8] = {a0.x, a0.y, a0.z, a0.w, a1.x, a1.y, a1.z, a1.w};
        float br[8] = {b0.x, b0.y, b0.z, b0.w, b1.x, b1.y, b1.z, b1.w};
        #pragma unroll
        for (int i = 0; i < 8; i++)
            #pragma unroll
            for (int j = 0; j < 8; j++)
                acc[i][j] = fmaf(ar[i], br[j], acc[i][j]);
    }

    // epilogue
    float S  = g_S[b];
    float cb = g_c[b];
    const float* v = g_v + b * N_;
    const unsigned int* mrow = mask + b * N_;

    float vm[8];
    #pragma unroll
    for (int j = 0; j < 8; j++) vm[j] = v[m0 + tx * 8 + j];

    #pragma unroll
    for (int i = 0; i < 8; i++) {
        int n = n0 + ty * 8 + i;
        float vn = v[n];
        bool mk = (mrow[n] != 0u);
        float4 o0, o1;
        if (mk) {
            float base = vn + cb;
            o0.x = fmaf(S, acc[i][0], base + vm[0]);
            o0.y = fmaf(S, acc[i][1], base + vm[1]);
            o0.z = fmaf(S, acc[i][2], base + vm[2]);
            o0.w = fmaf(S, acc[i][3], base + vm[3]);
            o1.x = fmaf(S, acc[i][4], base + vm[4]);
            o1.y = fmaf(S, acc[i][5], base + vm[5]);
            o1.z = fmaf(S, acc[i][6], base + vm[6]);
            o1.w = fmaf(S, acc[i][7], base + vm[7]);
        } else {
            o0.x = o0.y = o0.z = o0.w = 0.f;
            o1.x = o1.y = o1.z = o1.w = 0.f;
        }
        float* op = out + ((size_t)(b * N_ + n)) * N_ + m0 + tx * 8;
        *(float4*)(op)     = o0;
        *(float4*)(op + 4) = o1;
    }
}

// ---------------------------------------------------------------------------
extern "C" void kernel_launch(void* const* d_in, const int* in_sizes, int n_in,
                              void* d_out, int out_size)
{
    // Bind inputs by element count (all unique) — immune to metadata ordering.
    const float* first  = nullptr;   // 16*1024*64 = 1048576
    const float* second = nullptr;   // 16*64*32   = 32768
    const float* classc = nullptr;   // 16*10*32   = 5120
    const int*   y      = nullptr;   // 16
    const unsigned int* mask = nullptr; // 16*1024 = 16384
    const float* W1     = nullptr;   // 64*32 = 2048
    const float* b1     = nullptr;   // 64
    for (int i = 0; i < n_in; i++) {
        switch (in_sizes[i]) {
            case 1048576: first  = (const float*)d_in[i]; break;
            case 32768:   second = (const float*)d_in[i]; break;
            case 5120:    classc = (const float*)d_in[i]; break;
            case 16:      y      = (const int*)d_in[i]; break;
            case 16384:   mask   = (const unsigned int*)d_in[i]; break;
            case 2048:    W1     = (const float*)d_in[i]; break;
            case 64:      b1     = (const float*)d_in[i]; break;
            default: break;
        }
    }
    float* out = (float*)d_out;
    (void)out_size;

    prep_kernel<<<B_, 256>>>(second, classc, y, W1, b1);
    fc_kernel<<<(B_ * N_) / 8, 256>>>(first);

    cudaFuncSetAttribute(gram_kernel,
                         cudaFuncAttributeMaxDynamicSharedMemorySize,
                         64 * TILE * 2 * sizeof(float));
    dim3 grid(N_ / TILE, N_ / TILE, B_);
    gram_kernel<<<grid, 256, 64 * TILE * 2 * sizeof(float)>>>(mask, out);
}

// round 3
// speedup vs baseline: 1.5719x; 1.5719x over previous
#include <cuda_runtime.h>
#include <math.h>

#define B_   16
#define N_   1024
#define C2_  64
#define D_   32
#define H_   64
#define NC_  10
#define EPSF 1e-11f
#define TILE 128

__device__ float g_fc[B_ * N_ * H_];   // relu(first_capsule)
__device__ float g_v[B_ * N_];         // fc_n . u
__device__ float g_u[B_ * H_];         // sum_k scale_k * sec_k
__device__ float g_S[B_];              // sum_k scale_k
__device__ float g_c[B_];              // sum_k scale_k * |sec_k|^2

// ---------------------------------------------------------------------------
// Kernel 1: per-batch prep (parallel top-8 via rank counting).
// ---------------------------------------------------------------------------
__global__ __launch_bounds__(256) void prep_kernel(
    const float* __restrict__ second, const float* __restrict__ classc,
    const int* __restrict__ y, const float* __restrict__ W1,
    const float* __restrict__ b1)
{
    int b = blockIdx.x;
    int t = threadIdx.x;

    __shared__ float s_sn[C2_];
    __shared__ float s_scu[C2_][D_];
    __shared__ float s_secin[9][D_];
    __shared__ float s_scale[9];
    __shared__ float s_sec[9][H_];

    if (t < C2_) {
        const float* p = second + (b * C2_ + t) * D_;
        float sn = 0.f;
        #pragma unroll
        for (int d = 0; d < D_; d++) { float x = p[d]; sn += x * x; }
        s_sn[t] = sn;
        float inv = 1.0f / sqrtf(sn + EPSF);
        #pragma unroll
        for (int d = 0; d < D_; d++) s_scu[t][d] = p[d] * inv;
    }
    __syncthreads();

    if (t < C2_) {
        // rank of my sn (descending, ties by lower index first)
        float mysn = s_sn[t];
        int rank = 0;
        #pragma unroll
        for (int c = 0; c < C2_; c++) {
            float o = s_sn[c];
            rank += (o > mysn) || (o == mysn && c < t);
        }
        if (rank < 8) {     // selected; slot order irrelevant (we sum over k)
            s_scale[rank] = mysn / (1.f + mysn);
            #pragma unroll
            for (int d = 0; d < D_; d++) s_secin[rank][d] = s_scu[t][d];
        }
    } else if (t == C2_) {
        // true-class capsule; robust to int32 or float32 encoding of y
        int yb = y[b];
        if ((unsigned)yb >= (unsigned)NC_) {
            float yf = __int_as_float(yb);
            yb = (int)yf;
            if ((unsigned)yb >= (unsigned)NC_) yb = 0;
        }
        const float* cp = classc + (b * NC_ + yb) * D_;
        float sn = 0.f;
        for (int d = 0; d < D_; d++) sn += cp[d] * cp[d];
        float inv = 1.f / sqrtf(sn + EPSF);
        for (int d = 0; d < D_; d++) s_secin[8][d] = cp[d] * inv;
        s_scale[8] = sn / (1.f + sn);
    }
    __syncthreads();

    // sec[k][h] = relu(secin[k] . W1[h] + b1[h]) ; 576 outputs
    for (int o = t; o < 9 * H_; o += 256) {
        int k = o / H_, h = o % H_;
        float acc = b1[h];
        #pragma unroll
        for (int d = 0; d < D_; d++) acc += s_secin[k][d] * W1[h * D_ + d];
        s_sec[k][h] = fmaxf(acc, 0.f);
    }
    __syncthreads();

    if (t < H_) {
        float uh = 0.f;
        #pragma unroll
        for (int k = 0; k < 9; k++) uh += s_scale[k] * s_sec[k][t];
        g_u[b * H_ + t] = uh;
    }
    if (t == 0) {
        float S = 0.f, cb = 0.f;
        for (int k = 0; k < 9; k++) {
            S += s_scale[k];
            float ss = 0.f;
            for (int h = 0; h < H_; h++) ss += s_sec[k][h] * s_sec[k][h];
            cb += s_scale[k] * ss;
        }
        g_S[b] = S;
        g_c[b] = cb;
    }
}

// ---------------------------------------------------------------------------
// Kernel 2: fc = relu(first_capsule) ; v[b,n] = fc_n . u[b]
// ---------------------------------------------------------------------------
__global__ __launch_bounds__(256) void fc_kernel(const float* __restrict__ first)
{
    int gwarp = (blockIdx.x * blockDim.x + threadIdx.x) >> 5;
    int lane  = threadIdx.x & 31;
    if (gwarp >= B_ * N_) return;
    int b = gwarp >> 10;

    const float* p = first + (size_t)gwarp * H_;
    float f0 = fmaxf(p[lane], 0.f);
    float f1 = fmaxf(p[lane + 32], 0.f);
    g_fc[(size_t)gwarp * H_ + lane]      = f0;
    g_fc[(size_t)gwarp * H_ + lane + 32] = f1;

    float partial = f0 * g_u[b * H_ + lane] + f1 * g_u[b * H_ + lane + 32];
    #pragma unroll
    for (int o = 16; o; o >>= 1) partial += __shfl_xor_sync(0xFFFFFFFFu, partial, o);
    if (lane == 0) g_v[gwarp] = partial;
}

// ---------------------------------------------------------------------------
// Kernel 3: symmetric Gram with fused epilogue + row mask.
//   out[b,n,m] = mask[b,n] ? S*(fc_n.fc_m) + v[n] + v[m] + c : 0
// Only tiles nt<=mt are computed (36 of 64); off-diagonal blocks also emit the
// transposed tile straight from registers (acc[0..3][j] are 4 consecutive
// output columns -> float4 stores).
// Fragment mapping uses split-4 columns (tx*4 and 64+tx*4) so each 8-lane
// LDS.128 phase spans all 32 banks (conflict-free).
// ---------------------------------------------------------------------------
__global__ __launch_bounds__(256) void gram_kernel(
    const unsigned int* __restrict__ mask, float* __restrict__ out)
{
    extern __shared__ float smem[];
    float* As = smem;                 // [64][128] k-major
    float* Bs = smem + 64 * TILE;     // [64][128] k-major

    // decode triangular tile index: blockIdx.x in [0,36)
    int rem = blockIdx.x;
    int nt = 0;
    while (rem >= 8 - nt) { rem -= 8 - nt; nt++; }
    int mt = nt + rem;
    int b = blockIdx.z;
    int t = threadIdx.x;

    const float* fc = g_fc + (size_t)b * N_ * H_;
    int n0 = nt * TILE;
    int m0 = mt * TILE;

    // load both 128x64 tiles transposed into k-major smem
    #pragma unroll
    for (int it = 0; it < 8; it++) {
        int flat = t + it * 256;
        int row  = flat & 127;
        int kq   = flat >> 7;
        float4 va = *(const float4*)(fc + (size_t)(n0 + row) * H_ + kq * 4);
        As[(kq * 4 + 0) * TILE + row] = va.x;
        As[(kq * 4 + 1) * TILE + row] = va.y;
        As[(kq * 4 + 2) * TILE + row] = va.z;
        As[(kq * 4 + 3) * TILE + row] = va.w;
        float4 vb = *(const float4*)(fc + (size_t)(m0 + row) * H_ + kq * 4);
        Bs[(kq * 4 + 0) * TILE + row] = vb.x;
        Bs[(kq * 4 + 1) * TILE + row] = vb.y;
        Bs[(kq * 4 + 2) * TILE + row] = vb.z;
        Bs[(kq * 4 + 3) * TILE + row] = vb.w;
    }
    __syncthreads();

    int tx = t & 15;
    int ty = t >> 4;

    float acc[8][8];
    #pragma unroll
    for (int i = 0; i < 8; i++)
        #pragma unroll
        for (int j = 0; j < 8; j++) acc[i][j] = 0.f;

    #pragma unroll 4
    for (int kk = 0; kk < 64; kk++) {
        float4 a0 = *(const float4*)(As + kk * TILE + ty * 4);
        float4 a1 = *(const float4*)(As + kk * TILE + 64 + ty * 4);
        float4 b0 = *(const float4*)(Bs + kk * TILE + tx * 4);
        float4 b1 = *(const float4*)(Bs + kk * TILE + 64 + tx * 4);
        float ar[8] = {a0.x, a0.y, a0.z, a0.w, a1.x, a1.y, a1.z, a1.w};
        float br[8] = {b0.x, b0.y, b0.z, b0.w, b1.x, b1.y, b1.z, b1.w};
        #pragma unroll
        for (int i = 0; i < 8; i++)
            #pragma unroll
            for (int j = 0; j < 8; j++)
                acc[i][j] = fmaf(ar[i], br[j], acc[i][j]);
    }

    float S  = g_S[b];
    float cb = g_c[b];
    const float* v = g_v + b * N_;
    const unsigned int* mrow = mask + b * N_;

    // row/col index helpers for split-4 mapping
    int R0 = ty * 4, R1 = 64 + ty * 4;   // rows: R0+i (i<4), R1+(i-4)
    int C0 = tx * 4, C1 = 64 + tx * 4;   // cols: C0+j (j<4), C1+(j-4)

    float vm[8], vn[8];
    #pragma unroll
    for (int j = 0; j < 8; j++) vm[j] = v[m0 + (j < 4 ? C0 + j : C1 + j - 4)];
    #pragma unroll
    for (int i = 0; i < 8; i++) vn[i] = v[n0 + (i < 4 ? R0 + i : R1 + i - 4)];

    // normal tile: rows n, mask[n]
    #pragma unroll
    for (int i = 0; i < 8; i++) {
        int n = n0 + (i < 4 ? R0 + i : R1 + i - 4);
        bool mk = (mrow[n] != 0u);
        float base = vn[i] + cb;
        float4 o0, o1;
        if (mk) {
            o0.x = fmaf(S, acc[i][0], base + vm[0]);
            o0.y = fmaf(S, acc[i][1], base + vm[1]);
            o0.z = fmaf(S, acc[i][2], base + vm[2]);
            o0.w = fmaf(S, acc[i][3], base + vm[3]);
            o1.x = fmaf(S, acc[i][4], base + vm[4]);
            o1.y = fmaf(S, acc[i][5], base + vm[5]);
            o1.z = fmaf(S, acc[i][6], base + vm[6]);
            o1.w = fmaf(S, acc[i][7], base + vm[7]);
        } else {
            o0.x = o0.y = o0.z = o0.w = 0.f;
            o1.x = o1.y = o1.z = o1.w = 0.f;
        }
        float* op = out + ((size_t)(b * N_ + n)) * N_ + m0;
        *(float4*)(op + C0) = o0;
        *(float4*)(op + C1) = o1;
    }

    // transposed tile (off-diagonal only): rows m, mask[m]
    if (nt != mt) {
        #pragma unroll
        for (int j = 0; j < 8; j++) {
            int m = m0 + (j < 4 ? C0 + j : C1 + j - 4);
            bool mk = (mrow[m] != 0u);
            float base = vm[j] + cb;
            float4 o0, o1;
            if (mk) {
                o0.x = fmaf(S, acc[0][j], base + vn[0]);
                o0.y = fmaf(S, acc[1][j], base + vn[1]);
                o0.z = fmaf(S, acc[2][j], base + vn[2]);
                o0.w = fmaf(S, acc[3][j], base + vn[3]);
                o1.x = fmaf(S, acc[4][j], base + vn[4]);
                o1.y = fmaf(S, acc[5][j], base + vn[5]);
                o1.z = fmaf(S, acc[6][j], base + vn[6]);
                o1.w = fmaf(S, acc[7][j], base + vn[7]);
            } else {
                o0.x = o0.y = o0.z = o0.w = 0.f;
                o1.x = o1.y = o1.z = o1.w = 0.f;
            }
            float* op = out + ((size_t)(b * N_ + m)) * N_ + n0;
            *(float4*)(op + R0) = o0;
            *(float4*)(op + R1) = o1;
        }
    }
}

// ---------------------------------------------------------------------------
extern "C" void kernel_launch(void* const* d_in, const int* in_sizes, int n_in,
                              void* d_out, int out_size)
{
    const float* first  = nullptr;
    const float* second = nullptr;
    const float* classc = nullptr;
    const int*   y      = nullptr;
    const unsigned int* mask = nullptr;
    const float* W1     = nullptr;
    const float* b1     = nullptr;
    for (int i = 0; i < n_in; i++) {
        switch (in_sizes[i]) {
            case 1048576: first  = (const float*)d_in[i]; break;
            case 32768:   second = (const float*)d_in[i]; break;
            case 5120:    classc = (const float*)d_in[i]; break;
            case 16:      y      = (const int*)d_in[i]; break;
            case 16384:   mask   = (const unsigned int*)d_in[i]; break;
            case 2048:    W1     = (const float*)d_in[i]; break;
            case 64:      b1     = (const float*)d_in[i]; break;
            default: break;
        }
    }
    float* out = (float*)d_out;
    (void)out_size;

    prep_kernel<<<B_, 256>>>(second, classc, y, W1, b1);
    fc_kernel<<<(B_ * N_) / 8, 256>>>(first);

    cudaFuncSetAttribute(gram_kernel,
                         cudaFuncAttributeMaxDynamicSharedMemorySize,
                         64 * TILE * 2 * sizeof(float));
    dim3 grid(36, 1, B_);
    gram_kernel<<<grid, 256, 64 * TILE * 2 * sizeof(float)>>>(mask, out);
}

// round 4
// speedup vs baseline: 1.6842x; 1.0714x over previous
#include <cuda_runtime.h>
#include <math.h>

#define B_   16
#define N_   1024
#define C2_  64
#define D_   32
#define H_   64
#define NC_  10
#define EPSF 1e-11f
#define TILE 128

__device__ float g_fc[B_ * N_ * H_];   // relu(first_capsule)
__device__ float g_v[B_ * N_];         // fc_n . u
__device__ float g_u[B_ * H_];         // sum_k scale_k * sec_k
__device__ float g_S[B_];              // sum_k scale_k
__device__ float g_c[B_];              // sum_k scale_k * |sec_k|^2

// packed fp32x2 FMA: acc = a*b + acc (elementwise on 2-lane packs)
#define FMA2(acc, a, b) \
    asm("fma.rn.f32x2 %0, %1, %2, %0;" : "+l"(acc) : "l"(a), "l"(b))

// ---------------------------------------------------------------------------
// Kernel 1: per-batch prep (parallel top-8 via rank counting, parallel tail).
// ---------------------------------------------------------------------------
__global__ __launch_bounds__(256) void prep_kernel(
    const float* __restrict__ second, const float* __restrict__ classc,
    const int* __restrict__ y, const float* __restrict__ W1,
    const float* __restrict__ b1)
{
    int b = blockIdx.x;
    int t = threadIdx.x;

    __shared__ float s_sn[C2_];
    __shared__ float s_scu[C2_][D_];
    __shared__ float s_secin[9][D_];
    __shared__ float s_scale[9];
    __shared__ float s_sec[9][H_];
    __shared__ float s_red[H_];

    if (t < C2_) {
        const float* p = second + (b * C2_ + t) * D_;
        float sn = 0.f;
        #pragma unroll
        for (int d = 0; d < D_; d++) { float x = p[d]; sn += x * x; }
        s_sn[t] = sn;
        float inv = 1.0f / sqrtf(sn + EPSF);
        #pragma unroll
        for (int d = 0; d < D_; d++) s_scu[t][d] = p[d] * inv;
    }
    __syncthreads();

    if (t < C2_) {
        float mysn = s_sn[t];
        int rank = 0;
        #pragma unroll
        for (int c = 0; c < C2_; c++) {
            float o = s_sn[c];
            rank += (o > mysn) || (o == mysn && c < t);
        }
        if (rank < 8) {     // selected; slot order irrelevant (we sum over k)
            s_scale[rank] = mysn / (1.f + mysn);
            #pragma unroll
            for (int d = 0; d < D_; d++) s_secin[rank][d] = s_scu[t][d];
        }
    } else if (t == C2_) {
        // true-class capsule; robust to int32 or float32 encoding of y
        int yb = y[b];
        if ((unsigned)yb >= (unsigned)NC_) {
            float yf = __int_as_float(yb);
            yb = (int)yf;
            if ((unsigned)yb >= (unsigned)NC_) yb = 0;
        }
        const float* cp = classc + (b * NC_ + yb) * D_;
        float sn = 0.f;
        for (int d = 0; d < D_; d++) sn += cp[d] * cp[d];
        float inv = 1.f / sqrtf(sn + EPSF);
        for (int d = 0; d < D_; d++) s_secin[8][d] = cp[d] * inv;
        s_scale[8] = sn / (1.f + sn);
    }
    __syncthreads();

    // sec[k][h] = relu(secin[k] . W1[h] + b1[h]) ; 576 outputs
    for (int o = t; o < 9 * H_; o += 256) {
        int k = o / H_, h = o % H_;
        float acc = b1[h];
        #pragma unroll
        for (int d = 0; d < D_; d++) acc += s_secin[k][d] * W1[h * D_ + d];
        s_sec[k][h] = fmaxf(acc, 0.f);
    }
    __syncthreads();

    if (t < H_) {
        float uh = 0.f, ch = 0.f;
        #pragma unroll
        for (int k = 0; k < 9; k++) {
            float sk = s_scale[k], sv = s_sec[k][t];
            uh += sk * sv;
            ch += sk * sv * sv;
        }
        g_u[b * H_ + t] = uh;
        s_red[t] = ch;
    }
    __syncthreads();
    if (t == 0) {
        float cb = 0.f;
        #pragma unroll
        for (int h = 0; h < H_; h++) cb += s_red[h];
        float S = 0.f;
        #pragma unroll
        for (int k = 0; k < 9; k++) S += s_scale[k];
        g_S[b] = S;
        g_c[b] = cb;
    }
}

// ---------------------------------------------------------------------------
// Kernel 2: fc = relu(first_capsule) ; v[b,n] = fc_n . u[b]
// ---------------------------------------------------------------------------
__global__ __launch_bounds__(256) void fc_kernel(const float* __restrict__ first)
{
    int gwarp = (blockIdx.x * blockDim.x + threadIdx.x) >> 5;
    int lane  = threadIdx.x & 31;
    if (gwarp >= B_ * N_) return;
    int b = gwarp >> 10;

    const float* p = first + (size_t)gwarp * H_;
    float f0 = fmaxf(p[lane], 0.f);
    float f1 = fmaxf(p[lane + 32], 0.f);
    g_fc[(size_t)gwarp * H_ + lane]      = f0;
    g_fc[(size_t)gwarp * H_ + lane + 32] = f1;

    float partial = f0 * g_u[b * H_ + lane] + f1 * g_u[b * H_ + lane + 32];
    #pragma unroll
    for (int o = 16; o; o >>= 1) partial += __shfl_xor_sync(0xFFFFFFFFu, partial, o);
    if (lane == 0) g_v[gwarp] = partial;
}

// ---------------------------------------------------------------------------
// Kernel 3: symmetric Gram, packed fp32x2 FMA mainloop, fused epilogue + mask.
//   out[b,n,m] = mask[b,n] ? S*(fc_n.fc_m) + v[n] + v[m] + c : 0
// Tiles nt<=mt only; off-diagonal blocks emit the transposed tile from regs.
// ---------------------------------------------------------------------------
__global__ __launch_bounds__(256) void gram_kernel(
    const unsigned int* __restrict__ mask, float* __restrict__ out)
{
    extern __shared__ float smem[];
    float* As = smem;                 // [64][128] k-major
    float* Bs = smem + 64 * TILE;     // [64][128] k-major

    int rem = blockIdx.x;             // triangular index in [0,36)
    int nt = 0;
    while (rem >= 8 - nt) { rem -= 8 - nt; nt++; }
    int mt = nt + rem;
    int b = blockIdx.z;
    int t = threadIdx.x;

    const float* fc = g_fc + (size_t)b * N_ * H_;
    int n0 = nt * TILE;
    int m0 = mt * TILE;

    #pragma unroll
    for (int it = 0; it < 8; it++) {
        int flat = t + it * 256;
        int row  = flat & 127;
        int kq   = flat >> 7;
        float4 va = *(const float4*)(fc + (size_t)(n0 + row) * H_ + kq * 4);
        As[(kq * 4 + 0) * TILE + row] = va.x;
        As[(kq * 4 + 1) * TILE + row] = va.y;
        As[(kq * 4 + 2) * TILE + row] = va.z;
        As[(kq * 4 + 3) * TILE + row] = va.w;
        float4 vb = *(const float4*)(fc + (size_t)(m0 + row) * H_ + kq * 4);
        Bs[(kq * 4 + 0) * TILE + row] = vb.x;
        Bs[(kq * 4 + 1) * TILE + row] = vb.y;
        Bs[(kq * 4 + 2) * TILE + row] = vb.z;
        Bs[(kq * 4 + 3) * TILE + row] = vb.w;
    }
    __syncthreads();

    int tx = t & 15;
    int ty = t >> 4;

    // acc2[i][jp] packs columns (2*jp, 2*jp+1) of the 8-wide j range
    unsigned long long acc2[8][4];
    #pragma unroll
    for (int i = 0; i < 8; i++)
        #pragma unroll
        for (int jp = 0; jp < 4; jp++) acc2[i][jp] = 0ull;

    #pragma unroll 4
    for (int kk = 0; kk < 64; kk++) {
        float4 a0 = *(const float4*)(As + kk * TILE + ty * 4);
        float4 a1 = *(const float4*)(As + kk * TILE + 64 + ty * 4);
        ulonglong2 bq0 = *(const ulonglong2*)(Bs + kk * TILE + tx * 4);
        ulonglong2 bq1 = *(const ulonglong2*)(Bs + kk * TILE + 64 + tx * 4);
        unsigned long long bp[4] = {bq0.x, bq0.y, bq1.x, bq1.y};
        float ar[8] = {a0.x, a0.y, a0.z, a0.w, a1.x, a1.y, a1.z, a1.w};
        #pragma unroll
        for (int i = 0; i < 8; i++) {
            unsigned long long ap;
            unsigned int au = __float_as_uint(ar[i]);
            asm("mov.b64 %0, {%1, %1};" : "=l"(ap) : "r"(au));
            #pragma unroll
            for (int jp = 0; jp < 4; jp++)
                FMA2(acc2[i][jp], ap, bp[jp]);
        }
    }

    // unpack accumulators
    float acc[8][8];
    #pragma unroll
    for (int i = 0; i < 8; i++)
        #pragma unroll
        for (int jp = 0; jp < 4; jp++) {
            float2 f2 = *(float2*)&acc2[i][jp];
            acc[i][2 * jp]     = f2.x;
            acc[i][2 * jp + 1] = f2.y;
        }

    float S  = g_S[b];
    float cb = g_c[b];
    const float* v = g_v + b * N_;
    const unsigned int* mrow = mask + b * N_;

    int R0 = ty * 4, R1 = 64 + ty * 4;
    int C0 = tx * 4, C1 = 64 + tx * 4;

    float vm[8], vn[8];
    #pragma unroll
    for (int j = 0; j < 8; j++) vm[j] = v[m0 + (j < 4 ? C0 + j : C1 + j - 4)];
    #pragma unroll
    for (int i = 0; i < 8; i++) vn[i] = v[n0 + (i < 4 ? R0 + i : R1 + i - 4)];

    #pragma unroll
    for (int i = 0; i < 8; i++) {
        int n = n0 + (i < 4 ? R0 + i : R1 + i - 4);
        bool mk = (mrow[n] != 0u);
        float base = vn[i] + cb;
        float4 o0, o1;
        if (mk) {
            o0.x = fmaf(S, acc[i][0], base + vm[0]);
            o0.y = fmaf(S, acc[i][1], base + vm[1]);
            o0.z = fmaf(S, acc[i][2], base + vm[2]);
            o0.w = fmaf(S, acc[i][3], base + vm[3]);
            o1.x = fmaf(S, acc[i][4], base + vm[4]);
            o1.y = fmaf(S, acc[i][5], base + vm[5]);
            o1.z = fmaf(S, acc[i][6], base + vm[6]);
            o1.w = fmaf(S, acc[i][7], base + vm[7]);
        } else {
            o0.x = o0.y = o0.z = o0.w = 0.f;
            o1.x = o1.y = o1.z = o1.w = 0.f;
        }
        float* op = out + ((size_t)(b * N_ + n)) * N_ + m0;
        *(float4*)(op + C0) = o0;
        *(float4*)(op + C1) = o1;
    }

    if (nt != mt) {
        #pragma unroll
        for (int j = 0; j < 8; j++) {
            int m = m0 + (j < 4 ? C0 + j : C1 + j - 4);
            bool mk = (mrow[m] != 0u);
            float base = vm[j] + cb;
            float4 o0, o1;
            if (mk) {
                o0.x = fmaf(S, acc[0][j], base + vn[0]);
                o0.y = fmaf(S, acc[1][j], base + vn[1]);
                o0.z = fmaf(S, acc[2][j], base + vn[2]);
                o0.w = fmaf(S, acc[3][j], base + vn[3]);
                o1.x = fmaf(S, acc[4][j], base + vn[4]);
                o1.y = fmaf(S, acc[5][j], base + vn[5]);
                o1.z = fmaf(S, acc[6][j], base + vn[6]);
                o1.w = fmaf(S, acc[7][j], base + vn[7]);
            } else {
                o0.x = o0.y = o0.z = o0.w = 0.f;
                o1.x = o1.y = o1.z = o1.w = 0.f;
            }
            float* op = out + ((size_t)(b * N_ + m)) * N_ + n0;
            *(float4*)(op + R0) = o0;
            *(float4*)(op + R1) = o1;
        }
    }
}

// ---------------------------------------------------------------------------
extern "C" void kernel_launch(void* const* d_in, const int* in_sizes, int n_in,
                              void* d_out, int out_size)
{
    const float* first  = nullptr;
    const float* second = nullptr;
    const float* classc = nullptr;
    const int*   y      = nullptr;
    const unsigned int* mask = nullptr;
    const float* W1     = nullptr;
    const float* b1     = nullptr;
    for (int i = 0; i < n_in; i++) {
        switch (in_sizes[i]) {
            case 1048576: first  = (const float*)d_in[i]; break;
            case 32768:   second = (const float*)d_in[i]; break;
            case 5120:    classc = (const float*)d_in[i]; break;
            case 16:      y      = (const int*)d_in[i]; break;
            case 16384:   mask   = (const unsigned int*)d_in[i]; break;
            case 2048:    W1     = (const float*)d_in[i]; break;
            case 64:      b1     = (const float*)d_in[i]; break;
            default: break;
        }
    }
    float* out = (float*)d_out;
    (void)out_size;

    prep_kernel<<<B_, 256>>>(second, classc, y, W1, b1);
    fc_kernel<<<(B_ * N_) / 8, 256>>>(first);

    cudaFuncSetAttribute(gram_kernel,
                         cudaFuncAttributeMaxDynamicSharedMemorySize,
                         64 * TILE * 2 * sizeof(float));
    dim3 grid(36, 1, B_);
    gram_kernel<<<grid, 256, 64 * TILE * 2 * sizeof(float)>>>(mask, out);
}

// round 6
// speedup vs baseline: 2.3413x; 1.3902x over previous
#include <cuda_runtime.h>
#include <cuda_bf16.h>
#include <math.h>
#include <stdint.h>

#define B_   16
#define N_   1024
#define C2_  64
#define D_   32
#define H_   64
#define NC_  10
#define EPSF 1e-11f
#define PITCH 132           // staging pitch in floats (LDS.128 conflict-free)

// ---------------- scratch (static device globals) ----------------
__device__ unsigned int g_hi[B_ * N_ * (H_ / 2)];  // packed bf16x2 hi
__device__ unsigned int g_lo[B_ * N_ * (H_ / 2)];  // packed bf16x2 lo
__device__ float g_v[B_ * N_];
__device__ float g_u[B_ * H_];
__device__ float g_S[B_];
__device__ float g_c[B_];

__device__ __forceinline__ uint32_t smem_u32(const void* p) {
    uint32_t a;
    asm("{ .reg .u64 t; cvta.to.shared.u64 t, %1; cvt.u32.u64 %0, t; }"
        : "=r"(a) : "l"(p));
    return a;
}
#define SWZ(off) ((off) ^ (((off) >> 3) & 0x70))

__device__ __forceinline__ void ldm_x4(uint32_t* r, uint32_t addr) {
    asm volatile("ldmatrix.sync.aligned.m8n8.x4.shared.b16 {%0,%1,%2,%3}, [%4];"
        : "=r"(r[0]), "=r"(r[1]), "=r"(r[2]), "=r"(r[3]) : "r"(addr));
}
__device__ __forceinline__ void mma_bf16(float* c, const uint32_t* a,
                                         uint32_t b0, uint32_t b1) {
    asm volatile(
        "mma.sync.aligned.m16n8k16.row.col.f32.bf16.bf16.f32 "
        "{%0,%1,%2,%3}, {%4,%5,%6,%7}, {%8,%9}, {%0,%1,%2,%3};"
        : "+f"(c[0]), "+f"(c[1]), "+f"(c[2]), "+f"(c[3])
        : "r"(a[0]), "r"(a[1]), "r"(a[2]), "r"(a[3]), "r"(b0), "r"(b1));
}

// ---------------------------------------------------------------------------
// Kernel 1: per-batch prep
// ---------------------------------------------------------------------------
__global__ __launch_bounds__(256) void prep_kernel(
    const float* __restrict__ second, const float* __restrict__ classc,
    const int* __restrict__ y, const float* __restrict__ W1,
    const float* __restrict__ b1)
{
    int b = blockIdx.x;
    int t = threadIdx.x;

    __shared__ float s_W1[H_ * D_];
    __shared__ float s_sn[C2_];
    __shared__ float s_scu[C2_][D_];
    __shared__ float s_secin[9][D_];
    __shared__ float s_scale[9];
    __shared__ float s_sec[9][H_];
    __shared__ float s_red[H_];

    #pragma unroll
    for (int i = 0; i < 2; i++) {
        int q = t + i * 256;
        ((float4*)s_W1)[q] = ((const float4*)W1)[q];
    }

    if (t < C2_) {
        const float* p = second + (b * C2_ + t) * D_;
        float sn = 0.f;
        #pragma unroll
        for (int d = 0; d < D_; d++) { float x = p[d]; sn += x * x; }
        s_sn[t] = sn;
        float inv = 1.0f / sqrtf(sn + EPSF);
        #pragma unroll
        for (int d = 0; d < D_; d++) s_scu[t][d] = p[d] * inv;
    }
    __syncthreads();

    if (t < C2_) {
        float mysn = s_sn[t];
        int rank = 0;
        #pragma unroll
        for (int c = 0; c < C2_; c++) {
            float o = s_sn[c];
            rank += (o > mysn) || (o == mysn && c < t);
        }
        if (rank < 8) {
            s_scale[rank] = mysn / (1.f + mysn);
            #pragma unroll
            for (int d = 0; d < D_; d++) s_secin[rank][d] = s_scu[t][d];
        }
    } else if (t == C2_) {
        int yb = y[b];
        if ((unsigned)yb >= (unsigned)NC_) {
            float yf = __int_as_float(yb);
            yb = (int)yf;
            if ((unsigned)yb >= (unsigned)NC_) yb = 0;
        }
        const float* cp = classc + (b * NC_ + yb) * D_;
        float sn = 0.f;
        for (int d = 0; d < D_; d++) sn += cp[d] * cp[d];
        float inv = 1.f / sqrtf(sn + EPSF);
        for (int d = 0; d < D_; d++) s_secin[8][d] = cp[d] * inv;
        s_scale[8] = sn / (1.f + sn);
    }
    __syncthreads();

    for (int o = t; o < 9 * H_; o += 256) {
        int k = o / H_, h = o % H_;
        float acc = b1[h];
        #pragma unroll
        for (int d = 0; d < D_; d++) acc += s_secin[k][d] * s_W1[h * D_ + d];
        s_sec[k][h] = fmaxf(acc, 0.f);
    }
    __syncthreads();

    if (t < H_) {
        float uh = 0.f, ch = 0.f;
        #pragma unroll
        for (int k = 0; k < 9; k++) {
            float sk = s_scale[k], sv = s_sec[k][t];
            uh += sk * sv;
            ch += sk * sv * sv;
        }
        g_u[b * H_ + t] = uh;
        s_red[t] = ch;
    }
    __syncthreads();
    if (t == 0) {
        float cb = 0.f;
        #pragma unroll
        for (int h = 0; h < H_; h++) cb += s_red[h];
        float S = 0.f;
        #pragma unroll
        for (int k = 0; k < 9; k++) S += s_scale[k];
        g_S[b] = S;
        g_c[b] = cb;
    }
}

// ---------------------------------------------------------------------------
// Kernel 2: relu + bf16 hi/lo split + v[b,n] = fc_n . u[b]
// ---------------------------------------------------------------------------
__global__ __launch_bounds__(256) void fc_kernel(const float* __restrict__ first)
{
    int gwarp = (blockIdx.x * blockDim.x + threadIdx.x) >> 5;
    int lane  = threadIdx.x & 31;
    int b = gwarp >> 10;

    float2 f2 = ((const float2*)(first + (size_t)gwarp * H_))[lane];
    float x0 = fmaxf(f2.x, 0.f);
    float x1 = fmaxf(f2.y, 0.f);

    __nv_bfloat16 h0 = __float2bfloat16(x0);
    __nv_bfloat16 h1 = __float2bfloat16(x1);
    __nv_bfloat16 l0 = __float2bfloat16(x0 - __bfloat162float(h0));
    __nv_bfloat16 l1 = __float2bfloat16(x1 - __bfloat162float(h1));

    unsigned int hp = ((unsigned int)__bfloat16_as_ushort(h1) << 16) |
                       (unsigned int)__bfloat16_as_ushort(h0);
    unsigned int lp = ((unsigned int)__bfloat16_as_ushort(l1) << 16) |
                       (unsigned int)__bfloat16_as_ushort(l0);
    g_hi[(size_t)gwarp * 32 + lane] = hp;
    g_lo[(size_t)gwarp * 32 + lane] = lp;

    float partial = x0 * g_u[b * H_ + 2 * lane] + x1 * g_u[b * H_ + 2 * lane + 1];
    #pragma unroll
    for (int o = 16; o; o >>= 1) partial += __shfl_xor_sync(0xFFFFFFFFu, partial, o);
    if (lane == 0) g_v[gwarp] = partial;
}

// ---------------------------------------------------------------------------
// Kernel 3: symmetric Gram via mma.sync bf16 (hi/lo), staged epilogue + mask.
// smem: inputs Ahi/Alo/Bhi/Blo (4x16KB, SW128) -> reused as stagingN;
//       stagingT (off-diag) at +67584. Total 135168 B dynamic.
// ---------------------------------------------------------------------------
#define ST_N 0
#define ST_T 67584
#define SM_TOTAL 135168

__global__ __launch_bounds__(256) void gram_kernel(
    const unsigned int* __restrict__ mask, const float* __restrict__ vglob,
    float* __restrict__ out)
{
    extern __shared__ char smem[];
    uint32_t sb = smem_u32(smem);

    int rem = blockIdx.x, nt = 0;          // triangular decode, [0,36)
    while (rem >= 8 - nt) { rem -= 8 - nt; nt++; }
    int mt = nt + rem;
    int b = blockIdx.z;
    int t = threadIdx.x, w = t >> 5, l = t & 31;
    int n0 = nt * 128, m0 = mt * 128;
    bool offdiag = (nt != mt);

    // ---- load 4 bf16 tiles (128 x 128B) with SW128 swizzle ----
    const unsigned int* srcs[4] = {
        g_hi + ((size_t)(b * N_ + n0)) * 32,
        g_lo + ((size_t)(b * N_ + n0)) * 32,
        g_hi + ((size_t)(b * N_ + m0)) * 32,
        g_lo + ((size_t)(b * N_ + m0)) * 32 };
    const int dst[4] = { 0, 16384, 32768, 49152 };
    #pragma unroll
    for (int it = 0; it < 16; it++) {
        int flat = t + it * 256;
        int tile = flat >> 10, r2 = flat & 1023;
        int r = r2 >> 3, q = r2 & 7;
        uint4 val = *(const uint4*)(srcs[tile] + (size_t)r * 32 + q * 4);
        uint32_t off = SWZ((uint32_t)(r * 128 + q * 16));
        *(uint4*)(smem + dst[tile] + off) = val;
    }
    __syncthreads();

    // ---- mma mainloop ----
    int rw = w & 3;        // n row-block (32 rows)
    int cw = w >> 2;       // m col-block (64 cols)
    int g = l >> 3, lr = l & 7;

    float acc[2][8][4];
    #pragma unroll
    for (int i = 0; i < 2; i++)
        #pragma unroll
        for (int j = 0; j < 8; j++)
            #pragma unroll
            for (int q = 0; q < 4; q++) acc[i][j][q] = 0.f;

    uint32_t baseA = sb;            // hi; lo at +16384
    uint32_t baseB = sb + 32768;    // hi; lo at +16384

    // per-lane row/col contributions
    int arow = rw * 32 + (g & 1) * 8 + lr;      // + i*16
    int acol = (g >> 1) * 16;                   // + ks*32
    int brow = cw * 64 + (g >> 1) * 8 + lr;     // + jp*16
    int bcol = (g & 1) * 16;                    // + ks*32

    #pragma unroll
    for (int ks = 0; ks < 4; ks++) {
        uint32_t ahi[2][4], alo[2][4];
        #pragma unroll
        for (int i = 0; i < 2; i++) {
            uint32_t byte = SWZ((uint32_t)((arow + i * 16) * 128 + ks * 32 + acol));
            ldm_x4(ahi[i], baseA + byte);
            ldm_x4(alo[i], baseA + 16384 + byte);
        }
        #pragma unroll
        for (int jp = 0; jp < 4; jp++) {
            uint32_t bhi[4], blo[4];
            uint32_t byte = SWZ((uint32_t)((brow + jp * 16) * 128 + ks * 32 + bcol));
            ldm_x4(bhi, baseB + byte);
            ldm_x4(blo, baseB + 16384 + byte);
            #pragma unroll
            for (int i = 0; i < 2; i++) {
                mma_bf16(acc[i][2 * jp],     ahi[i], bhi[0], bhi[1]);
                mma_bf16(acc[i][2 * jp + 1], ahi[i], bhi[2], bhi[3]);
                mma_bf16(acc[i][2 * jp],     alo[i], bhi[0], bhi[1]);
                mma_bf16(acc[i][2 * jp + 1], alo[i], bhi[2], bhi[3]);
                mma_bf16(acc[i][2 * jp],     ahi[i], blo[0], blo[1]);
                mma_bf16(acc[i][2 * jp + 1], ahi[i], blo[2], blo[3]);
            }
        }
    }
    __syncthreads();   // inputs dead; smem becomes staging

    // ---- fragments -> staging ----
    float* stN = (float*)(smem + ST_N);    // [128][PITCH]
    float* stT = (float*)(smem + ST_T);
    #pragma unroll
    for (int i = 0; i < 2; i++)
        #pragma unroll
        for (int j = 0; j < 8; j++) {
            int r = rw * 32 + i * 16 + (l >> 2);
            int c = cw * 64 + j * 8 + (l & 3) * 2;
            *(float2*)&stN[r * PITCH + c]       = make_float2(acc[i][j][0], acc[i][j][1]);
            *(float2*)&stN[(r + 8) * PITCH + c] = make_float2(acc[i][j][2], acc[i][j][3]);
            if (offdiag) {
                stT[c * PITCH + r]           = acc[i][j][0];
                stT[(c + 1) * PITCH + r]     = acc[i][j][1];
                stT[c * PITCH + r + 8]       = acc[i][j][2];
                stT[(c + 1) * PITCH + r + 8] = acc[i][j][3];
            }
        }
    __syncthreads();

    // ---- coalesced epilogue + mask ----
    float S  = g_S[b];
    float cb = g_c[b];
    const float* v = vglob + b * N_;
    const unsigned int* mrow = mask + b * N_;

    {
        float4 vm4 = *(const float4*)(v + m0 + 4 * l);
        #pragma unroll
        for (int rr = 0; rr < 16; rr++) {
            int row = w * 16 + rr;
            int n = n0 + row;
            bool mk = (mrow[n] != 0u);
            float base = v[n] + cb;
            float4 g4 = *(const float4*)&stN[row * PITCH + 4 * l];
            float4 o;
            if (mk) {
                o.x = fmaf(S, g4.x, base + vm4.x);
                o.y = fmaf(S, g4.y, base + vm4.y);
                o.z = fmaf(S, g4.z, base + vm4.z);
                o.w = fmaf(S, g4.w, base + vm4.w);
            } else { o = make_float4(0.f, 0.f, 0.f, 0.f); }
            *(float4*)(out + ((size_t)(b * N_ + n)) * N_ + m0 + 4 * l) = o;
        }
    }
    if (offdiag) {
        float4 vn4 = *(const float4*)(v + n0 + 4 * l);
        #pragma unroll
        for (int rr = 0; rr < 16; rr++) {
            int row = w * 16 + rr;
            int m = m0 + row;
            bool mk = (mrow[m] != 0u);
            float base = v[m] + cb;
            float4 g4 = *(const float4*)&stT[row * PITCH + 4 * l];
            float4 o;
            if (mk) {
                o.x = fmaf(S, g4.x, base + vn4.x);
                o.y = fmaf(S, g4.y, base + vn4.y);
                o.z = fmaf(S, g4.z, base + vn4.z);
                o.w = fmaf(S, g4.w, base + vn4.w);
            } else { o = make_float4(0.f, 0.f, 0.f, 0.f); }
            *(float4*)(out + ((size_t)(b * N_ + m)) * N_ + n0 + 4 * l) = o;
        }
    }
}

// ---------------------------------------------------------------------------
extern "C" void kernel_launch(void* const* d_in, const int* in_sizes, int n_in,
                              void* d_out, int out_size)
{
    const float* first  = nullptr;
    const float* second = nullptr;
    const float* classc = nullptr;
    const int*   y      = nullptr;
    const unsigned int* mask = nullptr;
    const float* W1     = nullptr;
    const float* b1     = nullptr;
    for (int i = 0; i < n_in; i++) {
        switch (in_sizes[i]) {
            case 1048576: first  = (const float*)d_in[i]; break;
            case 32768:   second = (const float*)d_in[i]; break;
            case 5120:    classc = (const float*)d_in[i]; break;
            case 16:      y      = (const int*)d_in[i]; break;
            case 16384:   mask   = (const unsigned int*)d_in[i]; break;
            case 2048:    W1     = (const float*)d_in[i]; break;
            case 64:      b1     = (const float*)d_in[i]; break;
            default: break;
        }
    }
    float* out = (float*)d_out;
    (void)out_size;

    float* vptr = nullptr;
    cudaGetSymbolAddress((void**)&vptr, g_v);

    prep_kernel<<<B_, 256>>>(second, classc, y, W1, b1);
    fc_kernel<<<(B_ * N_) / 8, 256>>>(first);

    cudaFuncSetAttribute(gram_kernel,
                         cudaFuncAttributeMaxDynamicSharedMemorySize, SM_TOTAL);
    dim3 grid(36, 1, B_);
    gram_kernel<<<grid, 256, SM_TOTAL>>>(mask, vptr, out);
}

// round 7
// speedup vs baseline: 2.6198x; 1.1189x over previous
#include <cuda_runtime.h>
#include <cuda_bf16.h>
#include <math.h>
#include <stdint.h>

#define B_   16
#define N_   1024
#define C2_  64
#define D_   32
#define H_   64
#define NC_  10
#define EPSF 1e-11f
#define PITCH 132

// ---------------- scratch (static device globals) ----------------
__device__ unsigned int g_hi[B_ * N_ * (H_ / 2)];  // packed bf16x2 hi
__device__ unsigned int g_lo[B_ * N_ * (H_ / 2)];  // packed bf16x2 lo
__device__ float g_u[B_ * H_];
__device__ float g_S[B_];
__device__ float g_c[B_];

__device__ __forceinline__ uint32_t smem_u32(const void* p) {
    uint32_t a;
    asm("{ .reg .u64 t; cvta.to.shared.u64 t, %1; cvt.u32.u64 %0, t; }"
        : "=r"(a) : "l"(p));
    return a;
}
#define SWZ(off) ((off) ^ (((off) >> 3) & 0x70))

__device__ __forceinline__ void ldm_x4(uint32_t* r, uint32_t addr) {
    asm volatile("ldmatrix.sync.aligned.m8n8.x4.shared.b16 {%0,%1,%2,%3}, [%4];"
        : "=r"(r[0]), "=r"(r[1]), "=r"(r[2]), "=r"(r[3]) : "r"(addr));
}
__device__ __forceinline__ void mma_bf16(float* c, const uint32_t* a,
                                         uint32_t b0, uint32_t b1) {
    asm volatile(
        "mma.sync.aligned.m16n8k16.row.col.f32.bf16.bf16.f32 "
        "{%0,%1,%2,%3}, {%4,%5,%6,%7}, {%8,%9}, {%0,%1,%2,%3};"
        : "+f"(c[0]), "+f"(c[1]), "+f"(c[2]), "+f"(c[3])
        : "r"(a[0]), "r"(a[1]), "r"(a[2]), "r"(a[3]), "r"(b0), "r"(b1));
}

// ---------------------------------------------------------------------------
// Kernel 1 (merged): blocks < 2048 -> relu + bf16 hi/lo split
//                    blocks >= 2048 -> per-batch prep (b = blockIdx.x - 2048)
// ---------------------------------------------------------------------------
__global__ __launch_bounds__(256) void prep_fc_kernel(
    const float* __restrict__ first,
    const float* __restrict__ second, const float* __restrict__ classc,
    const int* __restrict__ y, const float* __restrict__ W1,
    const float* __restrict__ b1)
{
    int t = threadIdx.x;

    if (blockIdx.x < 2048) {
        // ---- fc split: one float2 per thread ----
        int gid = blockIdx.x * 256 + t;        // 0..524287 (= B*N*32)
        float2 f2 = ((const float2*)first)[gid];
        float x0 = fmaxf(f2.x, 0.f);
        float x1 = fmaxf(f2.y, 0.f);

        __nv_bfloat16 h0 = __float2bfloat16(x0);
        __nv_bfloat16 h1 = __float2bfloat16(x1);
        __nv_bfloat16 l0 = __float2bfloat16(x0 - __bfloat162float(h0));
        __nv_bfloat16 l1 = __float2bfloat16(x1 - __bfloat162float(h1));

        g_hi[gid] = ((unsigned int)__bfloat16_as_ushort(h1) << 16) |
                     (unsigned int)__bfloat16_as_ushort(h0);
        g_lo[gid] = ((unsigned int)__bfloat16_as_ushort(l1) << 16) |
                     (unsigned int)__bfloat16_as_ushort(l0);
        return;
    }

    // ---- prep ----
    int b = blockIdx.x - 2048;

    __shared__ float s_W1[H_ * D_];
    __shared__ float s_sn[C2_];
    __shared__ float s_scu[C2_][D_];
    __shared__ float s_secin[9][D_];
    __shared__ float s_scale[9];
    __shared__ float s_sec[9][H_];
    __shared__ float s_red[H_];

    #pragma unroll
    for (int i = 0; i < 2; i++) {
        int q = t + i * 256;
        ((float4*)s_W1)[q] = ((const float4*)W1)[q];
    }

    if (t < C2_) {
        const float* p = second + (b * C2_ + t) * D_;
        float sn = 0.f;
        #pragma unroll
        for (int d = 0; d < D_; d++) { float x = p[d]; sn += x * x; }
        s_sn[t] = sn;
        float inv = 1.0f / sqrtf(sn + EPSF);
        #pragma unroll
        for (int d = 0; d < D_; d++) s_scu[t][d] = p[d] * inv;
    }
    __syncthreads();

    if (t < C2_) {
        float mysn = s_sn[t];
        int rank = 0;
        #pragma unroll
        for (int c = 0; c < C2_; c++) {
            float o = s_sn[c];
            rank += (o > mysn) || (o == mysn && c < t);
        }
        if (rank < 8) {
            s_scale[rank] = mysn / (1.f + mysn);
            #pragma unroll
            for (int d = 0; d < D_; d++) s_secin[rank][d] = s_scu[t][d];
        }
    } else if (t == C2_) {
        int yb = y[b];
        if ((unsigned)yb >= (unsigned)NC_) {
            float yf = __int_as_float(yb);
            yb = (int)yf;
            if ((unsigned)yb >= (unsigned)NC_) yb = 0;
        }
        const float* cp = classc + (b * NC_ + yb) * D_;
        float sn = 0.f;
        for (int d = 0; d < D_; d++) sn += cp[d] * cp[d];
        float inv = 1.f / sqrtf(sn + EPSF);
        for (int d = 0; d < D_; d++) s_secin[8][d] = cp[d] * inv;
        s_scale[8] = sn / (1.f + sn);
    }
    __syncthreads();

    for (int o = t; o < 9 * H_; o += 256) {
        int k = o / H_, h = o % H_;
        float acc = b1[h];
        #pragma unroll
        for (int d = 0; d < D_; d++) acc += s_secin[k][d] * s_W1[h * D_ + d];
        s_sec[k][h] = fmaxf(acc, 0.f);
    }
    __syncthreads();

    if (t < H_) {
        float uh = 0.f, ch = 0.f;
        #pragma unroll
        for (int k = 0; k < 9; k++) {
            float sk = s_scale[k], sv = s_sec[k][t];
            uh += sk * sv;
            ch += sk * sv * sv;
        }
        g_u[b * H_ + t] = uh;
        s_red[t] = ch;
    }
    __syncthreads();
    if (t == 0) {
        float cb = 0.f;
        #pragma unroll
        for (int h = 0; h < H_; h++) cb += s_red[h];
        float S = 0.f;
        #pragma unroll
        for (int k = 0; k < 9; k++) S += s_scale[k];
        g_S[b] = S;
        g_c[b] = cb;
    }
}

// ---------------------------------------------------------------------------
// Kernel 2: symmetric Gram via mma.sync bf16 (hi/lo).
//   - v[n], v[m] computed in-kernel from smem tiles + u
//   - normal orientation stored DIRECTLY from fragments (full-sector STG.64)
//   - off-diagonal transposed tile staged in smem (pitch 132, overlaps inputs)
// smem: [0,65536) inputs (Ahi/Alo/Bhi/Blo, SW128); stT reuses [0,67584);
//       u at 67584, vn at 67840, vm at 68352. Total 68864 B.
// ---------------------------------------------------------------------------
#define SM_U   67584
#define SM_VN  67840
#define SM_VM  68352
#define SM_TOTAL 68864

__global__ __launch_bounds__(256) void gram_kernel(
    const unsigned int* __restrict__ mask, float* __restrict__ out)
{
    extern __shared__ char smem[];
    uint32_t sb = smem_u32(smem);

    int rem = blockIdx.x, nt = 0;          // triangular decode, [0,36)
    while (rem >= 8 - nt) { rem -= 8 - nt; nt++; }
    int mt = nt + rem;
    int b = blockIdx.z;
    int t = threadIdx.x, w = t >> 5, l = t & 31;
    int n0 = nt * 128, m0 = mt * 128;
    bool offdiag = (nt != mt);

    // stage u
    if (t < 64) ((float*)(smem + SM_U))[t] = g_u[b * H_ + t];

    // ---- load 4 bf16 tiles (128 x 128B) with SW128 swizzle ----
    const unsigned int* srcs[4] = {
        g_hi + ((size_t)(b * N_ + n0)) * 32,
        g_lo + ((size_t)(b * N_ + n0)) * 32,
        g_hi + ((size_t)(b * N_ + m0)) * 32,
        g_lo + ((size_t)(b * N_ + m0)) * 32 };
    const int dst[4] = { 0, 16384, 32768, 49152 };
    #pragma unroll
    for (int it = 0; it < 16; it++) {
        int flat = t + it * 256;
        int tile = flat >> 10, r2 = flat & 1023;
        int r = r2 >> 3, q = r2 & 7;
        uint4 val = *(const uint4*)(srcs[tile] + (size_t)r * 32 + q * 4);
        uint32_t off = SWZ((uint32_t)(r * 128 + q * 16));
        *(uint4*)(smem + dst[tile] + off) = val;
    }
    __syncthreads();

    // ---- compute v for the 128 A-rows (t<128) and 128 B-rows (t>=128) ----
    {
        int row = t & 127;
        int which = t >> 7;                       // 0 = A(n), 1 = B(m)
        const char* basep = smem + which * 32768;
        const float* u = (const float*)(smem + SM_U);
        float acc = 0.f;
        #pragma unroll
        for (int q = 0; q < 8; q++) {
            uint32_t off = SWZ((uint32_t)(row * 128 + q * 16));
            uint4 h4 = *(const uint4*)(basep + off);
            uint4 l4 = *(const uint4*)(basep + 16384 + off);
            const uint32_t hw[4] = {h4.x, h4.y, h4.z, h4.w};
            const uint32_t lw[4] = {l4.x, l4.y, l4.z, l4.w};
            #pragma unroll
            for (int w2 = 0; w2 < 4; w2++) {
                float2 hf = __bfloat1622float2(*(const __nv_bfloat162*)&hw[w2]);
                float2 lf = __bfloat1622float2(*(const __nv_bfloat162*)&lw[w2]);
                int k = q * 8 + w2 * 2;
                acc = fmaf(hf.x + lf.x, u[k],     acc);
                acc = fmaf(hf.y + lf.y, u[k + 1], acc);
            }
        }
        ((float*)(smem + (which ? SM_VM : SM_VN)))[row] = acc;
    }

    // ---- mma mainloop ----
    int rw = w & 3;        // n row-block (32 rows)
    int cw = w >> 2;       // m col-block (64 cols)
    int g = l >> 3, lr = l & 7;

    float acc[2][8][4];
    #pragma unroll
    for (int i = 0; i < 2; i++)
        #pragma unroll
        for (int j = 0; j < 8; j++)
            #pragma unroll
            for (int q = 0; q < 4; q++) acc[i][j][q] = 0.f;

    uint32_t baseA = sb;            // hi; lo at +16384
    uint32_t baseB = sb + 32768;    // hi; lo at +16384

    int arow = rw * 32 + (g & 1) * 8 + lr;
    int acol = (g >> 1) * 16;
    int brow = cw * 64 + (g >> 1) * 8 + lr;
    int bcol = (g & 1) * 16;

    #pragma unroll
    for (int ks = 0; ks < 4; ks++) {
        uint32_t ahi[2][4], alo[2][4];
        #pragma unroll
        for (int i = 0; i < 2; i++) {
            uint32_t byte = SWZ((uint32_t)((arow + i * 16) * 128 + ks * 32 + acol));
            ldm_x4(ahi[i], baseA + byte);
            ldm_x4(alo[i], baseA + 16384 + byte);
        }
        #pragma unroll
        for (int jp = 0; jp < 4; jp++) {
            uint32_t bhi[4], blo[4];
            uint32_t byte = SWZ((uint32_t)((brow + jp * 16) * 128 + ks * 32 + bcol));
            ldm_x4(bhi, baseB + byte);
            ldm_x4(blo, baseB + 16384 + byte);
            #pragma unroll
            for (int i = 0; i < 2; i++) {
                mma_bf16(acc[i][2 * jp],     ahi[i], bhi[0], bhi[1]);
                mma_bf16(acc[i][2 * jp + 1], ahi[i], bhi[2], bhi[3]);
                mma_bf16(acc[i][2 * jp],     alo[i], bhi[0], bhi[1]);
                mma_bf16(acc[i][2 * jp + 1], alo[i], bhi[2], bhi[3]);
                mma_bf16(acc[i][2 * jp],     ahi[i], blo[0], blo[1]);
                mma_bf16(acc[i][2 * jp + 1], ahi[i], blo[2], blo[3]);
            }
        }
    }
    __syncthreads();   // mainloop reads done; inputs dead; vn/vm/u valid

    float S  = g_S[b];
    float cb = g_c[b];
    const float* vn = (const float*)(smem + SM_VN);
    const float* vm = (const float*)(smem + SM_VM);
    const unsigned int* mrow = mask + b * N_;

    // ---- normal orientation: direct fragment stores ----
    {
        int rbase = rw * 32 + (l >> 2);
        float base4[4]; bool mk4[4];
        #pragma unroll
        for (int ii = 0; ii < 4; ii++) {
            int r = rbase + ii * 8;
            mk4[ii]   = (mrow[n0 + r] != 0u);
            base4[ii] = vn[r] + cb;
        }
        int cg = cw * 64 + (l & 3) * 2;
        #pragma unroll
        for (int j = 0; j < 8; j++) {
            int c = cg + j * 8;
            float2 vm2 = *(const float2*)&vm[c];
            #pragma unroll
            for (int ii = 0; ii < 4; ii++) {
                int i = ii >> 1, qq = (ii & 1) * 2;
                float2 o;
                if (mk4[ii]) {
                    o.x = fmaf(S, acc[i][j][qq],     base4[ii] + vm2.x);
                    o.y = fmaf(S, acc[i][j][qq + 1], base4[ii] + vm2.y);
                } else { o = make_float2(0.f, 0.f); }
                int n = n0 + rbase + ii * 8;
                *(float2*)(out + ((size_t)(b * N_ + n)) * N_ + m0 + c) = o;
            }
        }
    }

    // ---- off-diagonal: transpose via smem (reuses input region), then store
    if (offdiag) {
        float* stT = (float*)smem;     // [128][PITCH]
        #pragma unroll
        for (int i = 0; i < 2; i++)
            #pragma unroll
            for (int j = 0; j < 8; j++) {
                int r = rw * 32 + i * 16 + (l >> 2);
                int c = cw * 64 + j * 8 + (l & 3) * 2;
                stT[c * PITCH + r]           = acc[i][j][0];
                stT[(c + 1) * PITCH + r]     = acc[i][j][1];
                stT[c * PITCH + r + 8]       = acc[i][j][2];
                stT[(c + 1) * PITCH + r + 8] = acc[i][j][3];
            }
        __syncthreads();

        float4 vn4 = *(const float4*)&vn[4 * l];
        #pragma unroll
        for (int rr = 0; rr < 16; rr++) {
            int row = w * 16 + rr;                 // m-local row
            int m = m0 + row;
            bool mk = (mrow[m] != 0u);
            float base = vm[row] + cb;
            float4 g4 = *(const float4*)&stT[row * PITCH + 4 * l];
            float4 o;
            if (mk) {
                o.x = fmaf(S, g4.x, base + vn4.x);
                o.y = fmaf(S, g4.y, base + vn4.y);
                o.z = fmaf(S, g4.z, base + vn4.z);
                o.w = fmaf(S, g4.w, base + vn4.w);
            } else { o = make_float4(0.f, 0.f, 0.f, 0.f); }
            *(float4*)(out + ((size_t)(b * N_ + m)) * N_ + n0 + 4 * l) = o;
        }
    }
}

// ---------------------------------------------------------------------------
extern "C" void kernel_launch(void* const* d_in, const int* in_sizes, int n_in,
                              void* d_out, int out_size)
{
    const float* first  = nullptr;
    const float* second = nullptr;
    const float* classc = nullptr;
    const int*   y      = nullptr;
    const unsigned int* mask = nullptr;
    const float* W1     = nullptr;
    const float* b1     = nullptr;
    for (int i = 0; i < n_in; i++) {
        switch (in_sizes[i]) {
            case 1048576: first  = (const float*)d_in[i]; break;
            case 32768:   second = (const float*)d_in[i]; break;
            case 5120:    classc = (const float*)d_in[i]; break;
            case 16:      y      = (const int*)d_in[i]; break;
            case 16384:   mask   = (const unsigned int*)d_in[i]; break;
            case 2048:    W1     = (const float*)d_in[i]; break;
            case 64:      b1     = (const float*)d_in[i]; break;
            default: break;
        }
    }
    float* out = (float*)d_out;
    (void)out_size;

    prep_fc_kernel<<<2064, 256>>>(first, second, classc, y, W1, b1);

    cudaFuncSetAttribute(gram_kernel,
                         cudaFuncAttributeMaxDynamicSharedMemorySize, SM_TOTAL);
    dim3 grid(36, 1, B_);
    gram_kernel<<<grid, 256, SM_TOTAL>>>(mask, out);
}